// round 15
// baseline (speedup 1.0000x reference)
#include <cuda_runtime.h>
#include <cstdint>

// ---------------- problem constants ----------------
constexpr int N_NODES  = 100000;
constexpr int N_EDGES  = 3200000;
constexpr int N_GRAPHS = 64;
constexpr int IN_CH  = 64;
constexpr int HID_CH = 128;
constexpr int LAT    = 32;
constexpr float EPS  = 1e-5f;
constexpr int SCAN_CHUNK = 1024;
constexpr int NBLK = (N_NODES + SCAN_CHUNK - 1) / SCAN_CHUNK;   // 98

// ---------------- scratch (device globals) ----------------
__device__ __align__(16) int   g_count[N_NODES];
__device__ __align__(16) int   g_rowptr[N_NODES + 1];
__device__ __align__(16) int   g_cur[N_NODES];
__device__ __align__(16) int   g_src[N_EDGES];
__device__ __align__(16) int   g_bsum[NBLK];
__device__ __align__(16) int   g_boff[NBLK];
__device__ __align__(16) float g_dis[N_NODES];
__device__ __align__(16) float g_a  [(size_t)N_NODES * IN_CH];   // agg(x*dis)
__device__ __align__(16) float g_xs [(size_t)N_NODES * IN_CH];   // x * dis[row]
__device__ __align__(16) float g_h2 [(size_t)N_NODES * LAT];     // enc out (pre-agg)
__device__ __align__(16) float g_z  [(size_t)N_NODES * LAT];     // z_nodes
__device__ __align__(16) float g_s1[HID_CH];
__device__ __align__(16) float g_t1[HID_CH];
__device__ __align__(16) float g_s2[LAT];
__device__ __align__(16) float g_t2[LAT];
__device__ __align__(16) float g_sd[HID_CH];
__device__ __align__(16) float g_td[HID_CH];

// ---------------- zero counters + BN prep (fused) ----------------
__global__ void zero_prep_kernel(
    const float* __restrict__ conv1_b,
    const float* __restrict__ bn1_g, const float* __restrict__ bn1_b,
    const float* __restrict__ bn1_m, const float* __restrict__ bn1_v,
    const float* __restrict__ conv2_b,
    const float* __restrict__ bn2_g, const float* __restrict__ bn2_b,
    const float* __restrict__ bn2_m, const float* __restrict__ bn2_v,
    const float* __restrict__ fc1_b,
    const float* __restrict__ bnd_g, const float* __restrict__ bnd_b,
    const float* __restrict__ bnd_m, const float* __restrict__ bnd_v)
{
    int i = blockIdx.x * blockDim.x + threadIdx.x;
    if (i < N_NODES) g_count[i] = 0;
    if (blockIdx.x == 0) {
        int c = threadIdx.x;
        if (c < HID_CH) {
            float s = bn1_g[c] * rsqrtf(bn1_v[c] + EPS);
            g_s1[c] = s;
            g_t1[c] = (conv1_b[c] - bn1_m[c]) * s + bn1_b[c];
            float sd = bnd_g[c] * rsqrtf(bnd_v[c] + EPS);
            g_sd[c] = sd;
            g_td[c] = (fc1_b[c] - bnd_m[c]) * sd + bnd_b[c];
        }
        if (c < LAT) {
            float s = bn2_g[c] * rsqrtf(bn2_v[c] + EPS);
            g_s2[c] = s;
            g_t2[c] = (conv2_b[c] - bn2_m[c]) * s + bn2_b[c];
        }
    }
}

// ---------------- CSR build (edge_index is INT32; vectorized int4) ------------
__global__ void count_kernel(const int* __restrict__ ei) {
    int e4 = blockIdx.x * blockDim.x + threadIdx.x;
    if (e4 >= N_EDGES / 4) return;
    int4 c = ((const int4*)(ei + N_EDGES))[e4];
    atomicAdd(&g_count[c.x], 1);
    atomicAdd(&g_count[c.y], 1);
    atomicAdd(&g_count[c.z], 1);
    atomicAdd(&g_count[c.w], 1);
}

// per-chunk sums + dis + xs=x*dis (fused)
__global__ void scanA_kernel(const float* __restrict__ x) {
    __shared__ int sh[256];
    int t = threadIdx.x;
    int base = blockIdx.x * SCAN_CHUNK + t * 4;
    int s = 0;
    #pragma unroll
    for (int k = 0; k < 4; k++) {
        int i = base + k;
        if (i < N_NODES) {
            int d = g_count[i];
            s += d;
            g_dis[i] = d > 0 ? rsqrtf((float)d) : 0.0f;
        }
    }
    sh[t] = s; __syncthreads();
    for (int d = 128; d > 0; d >>= 1) {
        if (t < d) sh[t] += sh[t + d];
        __syncthreads();
    }
    if (t == 0) g_bsum[blockIdx.x] = sh[0];
    // scale x rows for this chunk (dis hot in L1/L2)
    int rbase = blockIdx.x * SCAN_CHUNK;
    for (int i = t; i < SCAN_CHUNK * (IN_CH / 4); i += 256) {
        int row = rbase + (i >> 4);
        if (row >= N_NODES) break;
        float d = g_dis[row];
        float4 v = ((const float4*)x)[(size_t)rbase * 16 + i];
        v.x *= d; v.y *= d; v.z *= d; v.w *= d;
        ((float4*)g_xs)[(size_t)rbase * 16 + i] = v;
    }
}

// parallel scan of the 98 chunk sums
__global__ void scanB_kernel() {
    __shared__ int sh[128];
    int t = threadIdx.x;
    int v = (t < NBLK) ? g_bsum[t] : 0;
    sh[t] = v; __syncthreads();
    for (int d = 1; d < 128; d <<= 1) {
        int tmp = (t >= d) ? sh[t - d] : 0;
        __syncthreads();
        sh[t] += tmp;
        __syncthreads();
    }
    if (t < NBLK) g_boff[t] = sh[t] - v;           // exclusive
    if (t == NBLK - 1) g_rowptr[N_NODES] = sh[t];
}

__global__ void scanC_kernel() {
    __shared__ int sh[256];
    int t = threadIdx.x;
    int base = blockIdx.x * SCAN_CHUNK + t * 4;
    int v[4]; int s = 0;
    #pragma unroll
    for (int k = 0; k < 4; k++) {
        int i = base + k;
        v[k] = (i < N_NODES) ? g_count[i] : 0;
        s += v[k];
    }
    sh[t] = s; __syncthreads();
    for (int d = 1; d < 256; d <<= 1) {
        int tmp = (t >= d) ? sh[t - d] : 0;
        __syncthreads();
        sh[t] += tmp;
        __syncthreads();
    }
    int off = g_boff[blockIdx.x] + sh[t] - s;   // exclusive
    #pragma unroll
    for (int k = 0; k < 4; k++) {
        int i = base + k;
        if (i < N_NODES) { g_rowptr[i] = off; g_cur[i] = off; off += v[k]; }
    }
}

__global__ void fill_kernel(const int* __restrict__ ei) {
    int e4 = blockIdx.x * blockDim.x + threadIdx.x;
    if (e4 >= N_EDGES / 4) return;
    int4 r = ((const int4*)ei)[e4];
    int4 c = ((const int4*)(ei + N_EDGES))[e4];
    g_src[atomicAdd(&g_cur[c.x], 1)] = r.x;
    g_src[atomicAdd(&g_cur[c.y], 1)] = r.y;
    g_src[atomicAdd(&g_cur[c.z], 1)] = r.z;
    g_src[atomicAdd(&g_cur[c.w], 1)] = r.w;
}

// ---------------- agg64: a[n] = dis[n] * sum xs[src]  (warp/node, prefetch) ---
__global__ void agg64_kernel() {
    int w = (blockIdx.x * blockDim.x + threadIdx.x) >> 5;
    if (w >= N_NODES) return;
    int lane = threadIdx.x & 31;
    int beg = g_rowptr[w], end = g_rowptr[w + 1];
    float2 acc = make_float2(0.f, 0.f);
    int i = beg;
    int myr = (i + lane < end) ? g_src[i + lane] : 0;      // prefetched batch
    for (; i + 32 <= end; i += 32) {
        int cur = myr;
        int nxt = i + 32;
        myr = (nxt + lane < end) ? g_src[nxt + lane] : 0;  // prefetch next
        #pragma unroll
        for (int j = 0; j < 32; j++) {
            int r = __shfl_sync(0xffffffffu, cur, j);
            float2 v = ((const float2*)g_xs)[r * (IN_CH / 2) + lane];
            acc.x += v.x;
            acc.y += v.y;
        }
    }
    if (i < end) {
        int cnt = end - i;
        #pragma unroll 4
        for (int j = 0; j < cnt; j++) {
            int r = __shfl_sync(0xffffffffu, myr, j);
            float2 v = ((const float2*)g_xs)[r * (IN_CH / 2) + lane];
            acc.x += v.x;
            acc.y += v.y;
        }
    }
    float dc = g_dis[w];
    acc.x *= dc; acc.y *= dc;
    ((float2*)g_a)[w * (IN_CH / 2) + lane] = acc;
}

// ---------------- agg32: z[n] = relu(bn2(dis[n] * sum h2[src])) ---------------
__global__ void agg32_kernel() {
    int w = (blockIdx.x * blockDim.x + threadIdx.x) >> 5;
    if (w >= N_NODES) return;
    int lane = threadIdx.x & 31;
    int beg = g_rowptr[w], end = g_rowptr[w + 1];
    float acc = 0.f;
    int i = beg;
    int myr = (i + lane < end) ? g_src[i + lane] : 0;
    for (; i + 32 <= end; i += 32) {
        int cur = myr;
        int nxt = i + 32;
        myr = (nxt + lane < end) ? g_src[nxt + lane] : 0;
        #pragma unroll
        for (int j = 0; j < 32; j++) {
            int r = __shfl_sync(0xffffffffu, cur, j);
            acc += g_h2[r * LAT + lane];
        }
    }
    if (i < end) {
        int cnt = end - i;
        #pragma unroll 4
        for (int j = 0; j < cnt; j++) {
            int r = __shfl_sync(0xffffffffu, myr, j);
            acc += g_h2[r * LAT + lane];
        }
    }
    acc *= g_dis[w];
    g_z[w * LAT + lane] = fmaxf(fmaf(acc, g_s2[lane], g_t2[lane]), 0.f);
}

// ---------------- fused encoder GEMM: h2 = relu(bn1(a@W1)) @ W2 * dis ---------
// (R11 plain-fmaf form — FFMA2 variant regressed and was reverted)
constexpr int ERPB = 32;
__global__ void __launch_bounds__(256) enc_gemm_kernel(const float* __restrict__ W1,
                                                       const float* __restrict__ W2)
{
    __shared__ alignas(16) float W2sh[HID_CH * LAT];     // 16 KB
    __shared__ alignas(16) float Xsh[ERPB * IN_CH];      // 8 KB
    __shared__ alignas(16) float B1sh[ERPB * 132];       // 16.5 KB (padded rows)
    const int tid = threadIdx.x;
    const int base = blockIdx.x * ERPB;

    for (int i = tid; i < HID_CH * LAT / 4; i += 256)
        ((float4*)W2sh)[i] = ((const float4*)W2)[i];
    for (int i = tid; i < ERPB * IN_CH / 4; i += 256) {
        int row = (i * 4) >> 6;
        float4 v = make_float4(0.f, 0.f, 0.f, 0.f);
        if (base + row < N_NODES) v = ((const float4*)g_a)[(size_t)base * 16 + i];
        ((float4*)Xsh)[i] = v;
    }
    __syncthreads();

    // stage 1: B1 = relu(bn1(X @ W1)); CQ=32, TM=4
    {
        int cx = tid & 31, ry = tid >> 5;
        float4 acc[4];
        #pragma unroll
        for (int m = 0; m < 4; m++) acc[m] = make_float4(0.f, 0.f, 0.f, 0.f);
        #pragma unroll 8
        for (int k = 0; k < IN_CH; k++) {
            float4 wv = ((const float4*)W1)[k * 32 + cx];     // L1-resident (32 KB)
            #pragma unroll
            for (int m = 0; m < 4; m++) {
                float xv = Xsh[(ry * 4 + m) * IN_CH + k];
                acc[m].x = fmaf(xv, wv.x, acc[m].x);
                acc[m].y = fmaf(xv, wv.y, acc[m].y);
                acc[m].z = fmaf(xv, wv.z, acc[m].z);
                acc[m].w = fmaf(xv, wv.w, acc[m].w);
            }
        }
        float4 sv = ((const float4*)g_s1)[cx];
        float4 tv = ((const float4*)g_t1)[cx];
        #pragma unroll
        for (int m = 0; m < 4; m++) {
            float4 o;
            o.x = fmaxf(fmaf(acc[m].x, sv.x, tv.x), 0.f);
            o.y = fmaxf(fmaf(acc[m].y, sv.y, tv.y), 0.f);
            o.z = fmaxf(fmaf(acc[m].z, sv.z, tv.z), 0.f);
            o.w = fmaxf(fmaf(acc[m].w, sv.w, tv.w), 0.f);
            ((float4*)(B1sh + (ry * 4 + m) * 132))[cx] = o;
        }
    }
    __syncthreads();

    // stage 2: h2 = (B1 @ W2) * dis[row]; CQ=8, TM=1
    {
        int cx = tid & 7, ry = tid >> 3;
        float4 acc = make_float4(0.f, 0.f, 0.f, 0.f);
        #pragma unroll 8
        for (int k = 0; k < HID_CH; k++) {
            float4 wv = ((const float4*)W2sh)[k * 8 + cx];
            float xv = B1sh[ry * 132 + k];
            acc.x = fmaf(xv, wv.x, acc.x);
            acc.y = fmaf(xv, wv.y, acc.y);
            acc.z = fmaf(xv, wv.z, acc.z);
            acc.w = fmaf(xv, wv.w, acc.w);
        }
        int row = base + ry;
        if (row < N_NODES) {
            float d = g_dis[row];
            acc.x *= d; acc.y *= d; acc.z *= d; acc.w *= d;
            ((float4*)g_h2)[(size_t)row * 8 + cx] = acc;
        }
    }
}

// ---------------- fused decoder GEMM: out = relu(bnd(z@W3)) @ W4 + b ----------
constexpr int DRPB = 32;
__global__ void __launch_bounds__(256) dec_gemm_kernel(const float* __restrict__ W3,
                                                       const float* __restrict__ W4,
                                                       const float* __restrict__ b4,
                                                       float* __restrict__ out)
{
    __shared__ alignas(16) float W3sh[LAT * HID_CH];     // 16 KB
    __shared__ alignas(16) float Zsh[DRPB * LAT];        // 4 KB
    __shared__ alignas(16) float Dsh[DRPB * 132];        // 16.5 KB
    const int tid = threadIdx.x;
    const int base = blockIdx.x * DRPB;

    for (int i = tid; i < LAT * HID_CH / 4; i += 256)
        ((float4*)W3sh)[i] = ((const float4*)W3)[i];
    for (int i = tid; i < DRPB * LAT / 4; i += 256) {
        int row = (i * 4) >> 5;
        float4 v = make_float4(0.f, 0.f, 0.f, 0.f);
        if (base + row < N_NODES) v = ((const float4*)g_z)[(size_t)base * 8 + i];
        ((float4*)Zsh)[i] = v;
    }
    __syncthreads();

    // stage 1: D = relu(bnd(Z @ W3)); CQ=32, TM=4
    {
        int cx = tid & 31, ry = tid >> 5;
        float4 acc[4];
        #pragma unroll
        for (int m = 0; m < 4; m++) acc[m] = make_float4(0.f, 0.f, 0.f, 0.f);
        #pragma unroll
        for (int k = 0; k < LAT; k++) {
            float4 wv = ((const float4*)W3sh)[k * 32 + cx];
            #pragma unroll
            for (int m = 0; m < 4; m++) {
                float xv = Zsh[(ry * 4 + m) * LAT + k];
                acc[m].x = fmaf(xv, wv.x, acc[m].x);
                acc[m].y = fmaf(xv, wv.y, acc[m].y);
                acc[m].z = fmaf(xv, wv.z, acc[m].z);
                acc[m].w = fmaf(xv, wv.w, acc[m].w);
            }
        }
        float4 sv = ((const float4*)g_sd)[cx];
        float4 tv = ((const float4*)g_td)[cx];
        #pragma unroll
        for (int m = 0; m < 4; m++) {
            float4 o;
            o.x = fmaxf(fmaf(acc[m].x, sv.x, tv.x), 0.f);
            o.y = fmaxf(fmaf(acc[m].y, sv.y, tv.y), 0.f);
            o.z = fmaxf(fmaf(acc[m].z, sv.z, tv.z), 0.f);
            o.w = fmaxf(fmaf(acc[m].w, sv.w, tv.w), 0.f);
            ((float4*)(Dsh + (ry * 4 + m) * 132))[cx] = o;
        }
    }
    __syncthreads();

    // stage 2: out = D @ W4 + b4; COUT=64, CQ=16, TM=2; W4 via L1 (32 KB)
    {
        int cx = tid & 15, ry = tid >> 4;
        float4 acc[2];
        acc[0] = make_float4(0.f, 0.f, 0.f, 0.f);
        acc[1] = make_float4(0.f, 0.f, 0.f, 0.f);
        #pragma unroll 8
        for (int k = 0; k < HID_CH; k++) {
            float4 wv = ((const float4*)W4)[k * 16 + cx];
            #pragma unroll
            for (int m = 0; m < 2; m++) {
                float xv = Dsh[(ry * 2 + m) * 132 + k];
                acc[m].x = fmaf(xv, wv.x, acc[m].x);
                acc[m].y = fmaf(xv, wv.y, acc[m].y);
                acc[m].z = fmaf(xv, wv.z, acc[m].z);
                acc[m].w = fmaf(xv, wv.w, acc[m].w);
            }
        }
        float4 bv = ((const float4*)b4)[cx];
        #pragma unroll
        for (int m = 0; m < 2; m++) {
            int row = base + ry * 2 + m;
            if (row < N_NODES) {
                float4 o = acc[m];
                o.x += bv.x; o.y += bv.y; o.z += bv.z; o.w += bv.w;
                ((float4*)out)[(size_t)row * 16 + cx] = o;
            }
        }
    }
}

// ---------------- graph mean pool: batch is SORTED int32 ----------------------
__global__ void pool_kernel(const int* __restrict__ batch, float* __restrict__ out) {
    int g = blockIdx.x;
    __shared__ int s_lo, s_hi;
    if (threadIdx.x == 0) {
        int a = 0, b = N_NODES;
        while (a < b) { int m = (a + b) >> 1; if (batch[m] < g) a = m + 1; else b = m; }
        s_lo = a;
        b = N_NODES;
        while (a < b) { int m = (a + b) >> 1; if (batch[m] < g + 1) a = m + 1; else b = m; }
        s_hi = a;
    }
    __syncthreads();
    int lo = s_lo, hi = s_hi;
    int lane = threadIdx.x & 31, wid = threadIdx.x >> 5;
    float acc = 0.f;
    for (int n = lo + wid; n < hi; n += 8)
        acc += g_z[(size_t)n * LAT + lane];
    __shared__ float sh[8][LAT];
    sh[wid][lane] = acc;
    __syncthreads();
    if (wid == 0) {
        float s = 0.f;
        #pragma unroll
        for (int k = 0; k < 8; k++) s += sh[k][lane];
        float cnt = (float)(hi - lo);
        out[g * LAT + lane] = s / fmaxf(cnt, 1.0f);
    }
}

// ---------------- launch: kernel launches ONLY ----------------
extern "C" void kernel_launch(void* const* d_in, const int* in_sizes, int n_in,
                              void* d_out, int out_size)
{
    const float* x     = (const float*)d_in[0];
    const int*   ei    = (const int*)d_in[1];      // int32
    const int*   batch = (const int*)d_in[2];      // int32
    const float* conv1_w = (const float*)d_in[3];
    const float* conv1_b = (const float*)d_in[4];
    const float* conv2_w = (const float*)d_in[5];
    const float* conv2_b = (const float*)d_in[6];
    const float* bn1_g = (const float*)d_in[7];
    const float* bn1_b = (const float*)d_in[8];
    const float* bn1_m = (const float*)d_in[9];
    const float* bn1_v = (const float*)d_in[10];
    const float* bn2_g = (const float*)d_in[11];
    const float* bn2_b = (const float*)d_in[12];
    const float* bn2_m = (const float*)d_in[13];
    const float* bn2_v = (const float*)d_in[14];
    const float* fc1_w = (const float*)d_in[15];
    const float* fc1_b = (const float*)d_in[16];
    const float* bnd_g = (const float*)d_in[17];
    const float* bnd_b = (const float*)d_in[18];
    const float* bnd_m = (const float*)d_in[19];
    const float* bnd_v = (const float*)d_in[20];
    const float* fc2_w = (const float*)d_in[21];
    const float* fc2_b = (const float*)d_in[22];
    float* out = (float*)d_out;

    zero_prep_kernel<<<(N_NODES + 255) / 256, 256>>>(
        conv1_b, bn1_g, bn1_b, bn1_m, bn1_v,
        conv2_b, bn2_g, bn2_b, bn2_m, bn2_v,
        fc1_b,   bnd_g, bnd_b, bnd_m, bnd_v);

    count_kernel<<<(N_EDGES / 4 + 255) / 256, 256>>>(ei);
    scanA_kernel<<<NBLK, 256>>>(x);         // dis + chunk sums + xs scaling
    scanB_kernel<<<1, 128>>>();
    scanC_kernel<<<NBLK, 256>>>();
    fill_kernel<<<(N_EDGES / 4 + 255) / 256, 256>>>(ei);

    // a = dis[n] * sum xs[src]
    agg64_kernel<<<(N_NODES * 32 + 255) / 256, 256>>>();
    // h2 = relu(bn1(a@W1 + cb1)) @ W2 * dis[row]   (fused encoder)
    enc_gemm_kernel<<<(N_NODES + ERPB - 1) / ERPB, 256>>>(conv1_w, conv2_w);
    // z = relu(bn2(dis[n] * sum h2[src] + cb2))
    agg32_kernel<<<(N_NODES * 32 + 255) / 256, 256>>>();
    // x_hat = relu(bnd(z@fc1 + b3)) @ fc2 + b4  -> d_out   (fused decoder)
    dec_gemm_kernel<<<(N_NODES + DRPB - 1) / DRPB, 256>>>(fc1_w, fc2_w, fc2_b, out);
    // z_graph -> d_out[6.4M:]
    pool_kernel<<<N_GRAPHS, 256>>>(batch, out + (size_t)N_NODES * IN_CH);
}

// round 16
// speedup vs baseline: 1.0453x; 1.0453x over previous
#include <cuda_runtime.h>
#include <cstdint>

// ---------------- problem constants ----------------
constexpr int N_NODES  = 100000;
constexpr int N_EDGES  = 3200000;
constexpr int N_GRAPHS = 64;
constexpr int IN_CH  = 64;
constexpr int HID_CH = 128;
constexpr int LAT    = 32;
constexpr float EPS  = 1e-5f;
constexpr int SCAN_CHUNK = 1024;
constexpr int NBLK = (N_NODES + SCAN_CHUNK - 1) / SCAN_CHUNK;   // 98

// ---------------- scratch (device globals) ----------------
__device__ __align__(16) int   g_count[N_NODES];
__device__ __align__(16) int   g_rowptr[N_NODES + 1];
__device__ __align__(16) int   g_cur[N_NODES];
__device__ __align__(16) int   g_src[N_EDGES];
__device__ __align__(16) int   g_bsum[NBLK];
__device__ __align__(16) int   g_boff[NBLK];
__device__ __align__(16) float g_dis[N_NODES];
__device__ __align__(16) float g_a  [(size_t)N_NODES * IN_CH];   // agg(x*dis)
__device__ __align__(16) float g_xs [(size_t)N_NODES * IN_CH];   // x * dis[row]
__device__ __align__(16) float g_h2 [(size_t)N_NODES * LAT];     // enc out (pre-agg)
__device__ __align__(16) float g_z  [(size_t)N_NODES * LAT];     // z_nodes
__device__ __align__(16) float g_s1[HID_CH];
__device__ __align__(16) float g_t1[HID_CH];
__device__ __align__(16) float g_s2[LAT];
__device__ __align__(16) float g_t2[LAT];
__device__ __align__(16) float g_sd[HID_CH];
__device__ __align__(16) float g_td[HID_CH];

// ---------------- zero counters + BN prep (fused) ----------------
__global__ void zero_prep_kernel(
    const float* __restrict__ conv1_b,
    const float* __restrict__ bn1_g, const float* __restrict__ bn1_b,
    const float* __restrict__ bn1_m, const float* __restrict__ bn1_v,
    const float* __restrict__ conv2_b,
    const float* __restrict__ bn2_g, const float* __restrict__ bn2_b,
    const float* __restrict__ bn2_m, const float* __restrict__ bn2_v,
    const float* __restrict__ fc1_b,
    const float* __restrict__ bnd_g, const float* __restrict__ bnd_b,
    const float* __restrict__ bnd_m, const float* __restrict__ bnd_v)
{
    int i = blockIdx.x * blockDim.x + threadIdx.x;
    if (i < N_NODES) g_count[i] = 0;
    if (blockIdx.x == 0) {
        int c = threadIdx.x;
        if (c < HID_CH) {
            float s = bn1_g[c] * rsqrtf(bn1_v[c] + EPS);
            g_s1[c] = s;
            g_t1[c] = (conv1_b[c] - bn1_m[c]) * s + bn1_b[c];
            float sd = bnd_g[c] * rsqrtf(bnd_v[c] + EPS);
            g_sd[c] = sd;
            g_td[c] = (fc1_b[c] - bnd_m[c]) * sd + bnd_b[c];
        }
        if (c < LAT) {
            float s = bn2_g[c] * rsqrtf(bn2_v[c] + EPS);
            g_s2[c] = s;
            g_t2[c] = (conv2_b[c] - bn2_m[c]) * s + bn2_b[c];
        }
    }
}

// ---------------- CSR build (edge_index is INT32; vectorized int4) ------------
__global__ void count_kernel(const int* __restrict__ ei) {
    int e4 = blockIdx.x * blockDim.x + threadIdx.x;
    if (e4 >= N_EDGES / 4) return;
    int4 c = ((const int4*)(ei + N_EDGES))[e4];
    atomicAdd(&g_count[c.x], 1);
    atomicAdd(&g_count[c.y], 1);
    atomicAdd(&g_count[c.z], 1);
    atomicAdd(&g_count[c.w], 1);
}

// per-chunk sums + dis (R11 form — no x-scaling here; 98-block grid is too
// narrow for a 51 MB streaming pass and sits on the scan critical path)
__global__ void scanA_kernel() {
    __shared__ int sh[256];
    int t = threadIdx.x;
    int base = blockIdx.x * SCAN_CHUNK + t * 4;
    int s = 0;
    #pragma unroll
    for (int k = 0; k < 4; k++) {
        int i = base + k;
        if (i < N_NODES) {
            int d = g_count[i];
            s += d;
            g_dis[i] = d > 0 ? rsqrtf((float)d) : 0.0f;
        }
    }
    sh[t] = s; __syncthreads();
    for (int d = 128; d > 0; d >>= 1) {
        if (t < d) sh[t] += sh[t + d];
        __syncthreads();
    }
    if (t == 0) g_bsum[blockIdx.x] = sh[0];
}

// parallel scan of the 98 chunk sums
__global__ void scanB_kernel() {
    __shared__ int sh[128];
    int t = threadIdx.x;
    int v = (t < NBLK) ? g_bsum[t] : 0;
    sh[t] = v; __syncthreads();
    for (int d = 1; d < 128; d <<= 1) {
        int tmp = (t >= d) ? sh[t - d] : 0;
        __syncthreads();
        sh[t] += tmp;
        __syncthreads();
    }
    if (t < NBLK) g_boff[t] = sh[t] - v;           // exclusive
    if (t == NBLK - 1) g_rowptr[N_NODES] = sh[t];
}

__global__ void scanC_kernel() {
    __shared__ int sh[256];
    int t = threadIdx.x;
    int base = blockIdx.x * SCAN_CHUNK + t * 4;
    int v[4]; int s = 0;
    #pragma unroll
    for (int k = 0; k < 4; k++) {
        int i = base + k;
        v[k] = (i < N_NODES) ? g_count[i] : 0;
        s += v[k];
    }
    sh[t] = s; __syncthreads();
    for (int d = 1; d < 256; d <<= 1) {
        int tmp = (t >= d) ? sh[t - d] : 0;
        __syncthreads();
        sh[t] += tmp;
        __syncthreads();
    }
    int off = g_boff[blockIdx.x] + sh[t] - s;   // exclusive
    #pragma unroll
    for (int k = 0; k < 4; k++) {
        int i = base + k;
        if (i < N_NODES) { g_rowptr[i] = off; g_cur[i] = off; off += v[k]; }
    }
}

__global__ void fill_kernel(const int* __restrict__ ei) {
    int e4 = blockIdx.x * blockDim.x + threadIdx.x;
    if (e4 >= N_EDGES / 4) return;
    int4 r = ((const int4*)ei)[e4];
    int4 c = ((const int4*)(ei + N_EDGES))[e4];
    g_src[atomicAdd(&g_cur[c.x], 1)] = r.x;
    g_src[atomicAdd(&g_cur[c.y], 1)] = r.y;
    g_src[atomicAdd(&g_cur[c.z], 1)] = r.z;
    g_src[atomicAdd(&g_cur[c.w], 1)] = r.w;
}

// ---------------- xs = x * dis[row]  (standalone, wide grid — R11 form) -------
__global__ void scale_x_kernel(const float* __restrict__ x) {
    int i = blockIdx.x * 256 + threadIdx.x;                // float4 index
    if (i >= N_NODES * (IN_CH / 4)) return;
    int row = i >> 4;
    float d = g_dis[row];
    float4 v = ((const float4*)x)[i];
    v.x *= d; v.y *= d; v.z *= d; v.w *= d;
    ((float4*)g_xs)[i] = v;
}

// ---------------- agg64: a[n] = dis[n] * sum xs[src]  (warp/node, prefetch) ---
__global__ void agg64_kernel() {
    int w = (blockIdx.x * blockDim.x + threadIdx.x) >> 5;
    if (w >= N_NODES) return;
    int lane = threadIdx.x & 31;
    int beg = g_rowptr[w], end = g_rowptr[w + 1];
    float2 acc = make_float2(0.f, 0.f);
    int i = beg;
    int myr = (i + lane < end) ? g_src[i + lane] : 0;      // prefetched batch
    for (; i + 32 <= end; i += 32) {
        int cur = myr;
        int nxt = i + 32;
        myr = (nxt + lane < end) ? g_src[nxt + lane] : 0;  // prefetch next
        #pragma unroll
        for (int j = 0; j < 32; j++) {
            int r = __shfl_sync(0xffffffffu, cur, j);
            float2 v = ((const float2*)g_xs)[r * (IN_CH / 2) + lane];
            acc.x += v.x;
            acc.y += v.y;
        }
    }
    if (i < end) {
        int cnt = end - i;
        #pragma unroll 4
        for (int j = 0; j < cnt; j++) {
            int r = __shfl_sync(0xffffffffu, myr, j);
            float2 v = ((const float2*)g_xs)[r * (IN_CH / 2) + lane];
            acc.x += v.x;
            acc.y += v.y;
        }
    }
    float dc = g_dis[w];
    acc.x *= dc; acc.y *= dc;
    ((float2*)g_a)[w * (IN_CH / 2) + lane] = acc;
}

// ---------------- agg32: z[n] = relu(bn2(dis[n] * sum h2[src])) ---------------
__global__ void agg32_kernel() {
    int w = (blockIdx.x * blockDim.x + threadIdx.x) >> 5;
    if (w >= N_NODES) return;
    int lane = threadIdx.x & 31;
    int beg = g_rowptr[w], end = g_rowptr[w + 1];
    float acc = 0.f;
    int i = beg;
    int myr = (i + lane < end) ? g_src[i + lane] : 0;
    for (; i + 32 <= end; i += 32) {
        int cur = myr;
        int nxt = i + 32;
        myr = (nxt + lane < end) ? g_src[nxt + lane] : 0;
        #pragma unroll
        for (int j = 0; j < 32; j++) {
            int r = __shfl_sync(0xffffffffu, cur, j);
            acc += g_h2[r * LAT + lane];
        }
    }
    if (i < end) {
        int cnt = end - i;
        #pragma unroll 4
        for (int j = 0; j < cnt; j++) {
            int r = __shfl_sync(0xffffffffu, myr, j);
            acc += g_h2[r * LAT + lane];
        }
    }
    acc *= g_dis[w];
    g_z[w * LAT + lane] = fmaxf(fmaf(acc, g_s2[lane], g_t2[lane]), 0.f);
}

// ---------------- fused encoder GEMM: h2 = relu(bn1(a@W1)) @ W2 * dis ---------
constexpr int ERPB = 32;
__global__ void __launch_bounds__(256) enc_gemm_kernel(const float* __restrict__ W1,
                                                       const float* __restrict__ W2)
{
    __shared__ alignas(16) float W2sh[HID_CH * LAT];     // 16 KB
    __shared__ alignas(16) float Xsh[ERPB * IN_CH];      // 8 KB
    __shared__ alignas(16) float B1sh[ERPB * 132];       // 16.5 KB (padded rows)
    const int tid = threadIdx.x;
    const int base = blockIdx.x * ERPB;

    for (int i = tid; i < HID_CH * LAT / 4; i += 256)
        ((float4*)W2sh)[i] = ((const float4*)W2)[i];
    for (int i = tid; i < ERPB * IN_CH / 4; i += 256) {
        int row = (i * 4) >> 6;
        float4 v = make_float4(0.f, 0.f, 0.f, 0.f);
        if (base + row < N_NODES) v = ((const float4*)g_a)[(size_t)base * 16 + i];
        ((float4*)Xsh)[i] = v;
    }
    __syncthreads();

    // stage 1: B1 = relu(bn1(X @ W1)); CQ=32, TM=4
    {
        int cx = tid & 31, ry = tid >> 5;
        float4 acc[4];
        #pragma unroll
        for (int m = 0; m < 4; m++) acc[m] = make_float4(0.f, 0.f, 0.f, 0.f);
        #pragma unroll 8
        for (int k = 0; k < IN_CH; k++) {
            float4 wv = ((const float4*)W1)[k * 32 + cx];     // L1-resident (32 KB)
            #pragma unroll
            for (int m = 0; m < 4; m++) {
                float xv = Xsh[(ry * 4 + m) * IN_CH + k];
                acc[m].x = fmaf(xv, wv.x, acc[m].x);
                acc[m].y = fmaf(xv, wv.y, acc[m].y);
                acc[m].z = fmaf(xv, wv.z, acc[m].z);
                acc[m].w = fmaf(xv, wv.w, acc[m].w);
            }
        }
        float4 sv = ((const float4*)g_s1)[cx];
        float4 tv = ((const float4*)g_t1)[cx];
        #pragma unroll
        for (int m = 0; m < 4; m++) {
            float4 o;
            o.x = fmaxf(fmaf(acc[m].x, sv.x, tv.x), 0.f);
            o.y = fmaxf(fmaf(acc[m].y, sv.y, tv.y), 0.f);
            o.z = fmaxf(fmaf(acc[m].z, sv.z, tv.z), 0.f);
            o.w = fmaxf(fmaf(acc[m].w, sv.w, tv.w), 0.f);
            ((float4*)(B1sh + (ry * 4 + m) * 132))[cx] = o;
        }
    }
    __syncthreads();

    // stage 2: h2 = (B1 @ W2) * dis[row]; CQ=8, TM=1
    {
        int cx = tid & 7, ry = tid >> 3;
        float4 acc = make_float4(0.f, 0.f, 0.f, 0.f);
        #pragma unroll 8
        for (int k = 0; k < HID_CH; k++) {
            float4 wv = ((const float4*)W2sh)[k * 8 + cx];
            float xv = B1sh[ry * 132 + k];
            acc.x = fmaf(xv, wv.x, acc.x);
            acc.y = fmaf(xv, wv.y, acc.y);
            acc.z = fmaf(xv, wv.z, acc.z);
            acc.w = fmaf(xv, wv.w, acc.w);
        }
        int row = base + ry;
        if (row < N_NODES) {
            float d = g_dis[row];
            acc.x *= d; acc.y *= d; acc.z *= d; acc.w *= d;
            ((float4*)g_h2)[(size_t)row * 8 + cx] = acc;
        }
    }
}

// ---------------- fused decoder GEMM: out = relu(bnd(z@W3)) @ W4 + b ----------
constexpr int DRPB = 32;
__global__ void __launch_bounds__(256) dec_gemm_kernel(const float* __restrict__ W3,
                                                       const float* __restrict__ W4,
                                                       const float* __restrict__ b4,
                                                       float* __restrict__ out)
{
    __shared__ alignas(16) float W3sh[LAT * HID_CH];     // 16 KB
    __shared__ alignas(16) float Zsh[DRPB * LAT];        // 4 KB
    __shared__ alignas(16) float Dsh[DRPB * 132];        // 16.5 KB
    const int tid = threadIdx.x;
    const int base = blockIdx.x * DRPB;

    for (int i = tid; i < LAT * HID_CH / 4; i += 256)
        ((float4*)W3sh)[i] = ((const float4*)W3)[i];
    for (int i = tid; i < DRPB * LAT / 4; i += 256) {
        int row = (i * 4) >> 5;
        float4 v = make_float4(0.f, 0.f, 0.f, 0.f);
        if (base + row < N_NODES) v = ((const float4*)g_z)[(size_t)base * 8 + i];
        ((float4*)Zsh)[i] = v;
    }
    __syncthreads();

    // stage 1: D = relu(bnd(Z @ W3)); CQ=32, TM=4
    {
        int cx = tid & 31, ry = tid >> 5;
        float4 acc[4];
        #pragma unroll
        for (int m = 0; m < 4; m++) acc[m] = make_float4(0.f, 0.f, 0.f, 0.f);
        #pragma unroll
        for (int k = 0; k < LAT; k++) {
            float4 wv = ((const float4*)W3sh)[k * 32 + cx];
            #pragma unroll
            for (int m = 0; m < 4; m++) {
                float xv = Zsh[(ry * 4 + m) * LAT + k];
                acc[m].x = fmaf(xv, wv.x, acc[m].x);
                acc[m].y = fmaf(xv, wv.y, acc[m].y);
                acc[m].z = fmaf(xv, wv.z, acc[m].z);
                acc[m].w = fmaf(xv, wv.w, acc[m].w);
            }
        }
        float4 sv = ((const float4*)g_sd)[cx];
        float4 tv = ((const float4*)g_td)[cx];
        #pragma unroll
        for (int m = 0; m < 4; m++) {
            float4 o;
            o.x = fmaxf(fmaf(acc[m].x, sv.x, tv.x), 0.f);
            o.y = fmaxf(fmaf(acc[m].y, sv.y, tv.y), 0.f);
            o.z = fmaxf(fmaf(acc[m].z, sv.z, tv.z), 0.f);
            o.w = fmaxf(fmaf(acc[m].w, sv.w, tv.w), 0.f);
            ((float4*)(Dsh + (ry * 4 + m) * 132))[cx] = o;
        }
    }
    __syncthreads();

    // stage 2: out = D @ W4 + b4; COUT=64, CQ=16, TM=2; W4 via L1 (32 KB)
    {
        int cx = tid & 15, ry = tid >> 4;
        float4 acc[2];
        acc[0] = make_float4(0.f, 0.f, 0.f, 0.f);
        acc[1] = make_float4(0.f, 0.f, 0.f, 0.f);
        #pragma unroll 8
        for (int k = 0; k < HID_CH; k++) {
            float4 wv = ((const float4*)W4)[k * 16 + cx];
            #pragma unroll
            for (int m = 0; m < 2; m++) {
                float xv = Dsh[(ry * 2 + m) * 132 + k];
                acc[m].x = fmaf(xv, wv.x, acc[m].x);
                acc[m].y = fmaf(xv, wv.y, acc[m].y);
                acc[m].z = fmaf(xv, wv.z, acc[m].z);
                acc[m].w = fmaf(xv, wv.w, acc[m].w);
            }
        }
        float4 bv = ((const float4*)b4)[cx];
        #pragma unroll
        for (int m = 0; m < 2; m++) {
            int row = base + ry * 2 + m;
            if (row < N_NODES) {
                float4 o = acc[m];
                o.x += bv.x; o.y += bv.y; o.z += bv.z; o.w += bv.w;
                ((float4*)out)[(size_t)row * 16 + cx] = o;
            }
        }
    }
}

// ---------------- graph mean pool: batch is SORTED int32 ----------------------
__global__ void pool_kernel(const int* __restrict__ batch, float* __restrict__ out) {
    int g = blockIdx.x;
    __shared__ int s_lo, s_hi;
    if (threadIdx.x == 0) {
        int a = 0, b = N_NODES;
        while (a < b) { int m = (a + b) >> 1; if (batch[m] < g) a = m + 1; else b = m; }
        s_lo = a;
        b = N_NODES;
        while (a < b) { int m = (a + b) >> 1; if (batch[m] < g + 1) a = m + 1; else b = m; }
        s_hi = a;
    }
    __syncthreads();
    int lo = s_lo, hi = s_hi;
    int lane = threadIdx.x & 31, wid = threadIdx.x >> 5;
    float acc = 0.f;
    for (int n = lo + wid; n < hi; n += 8)
        acc += g_z[(size_t)n * LAT + lane];
    __shared__ float sh[8][LAT];
    sh[wid][lane] = acc;
    __syncthreads();
    if (wid == 0) {
        float s = 0.f;
        #pragma unroll
        for (int k = 0; k < 8; k++) s += sh[k][lane];
        float cnt = (float)(hi - lo);
        out[g * LAT + lane] = s / fmaxf(cnt, 1.0f);
    }
}

// ---------------- launch: kernel launches ONLY ----------------
extern "C" void kernel_launch(void* const* d_in, const int* in_sizes, int n_in,
                              void* d_out, int out_size)
{
    const float* x     = (const float*)d_in[0];
    const int*   ei    = (const int*)d_in[1];      // int32
    const int*   batch = (const int*)d_in[2];      // int32
    const float* conv1_w = (const float*)d_in[3];
    const float* conv1_b = (const float*)d_in[4];
    const float* conv2_w = (const float*)d_in[5];
    const float* conv2_b = (const float*)d_in[6];
    const float* bn1_g = (const float*)d_in[7];
    const float* bn1_b = (const float*)d_in[8];
    const float* bn1_m = (const float*)d_in[9];
    const float* bn1_v = (const float*)d_in[10];
    const float* bn2_g = (const float*)d_in[11];
    const float* bn2_b = (const float*)d_in[12];
    const float* bn2_m = (const float*)d_in[13];
    const float* bn2_v = (const float*)d_in[14];
    const float* fc1_w = (const float*)d_in[15];
    const float* fc1_b = (const float*)d_in[16];
    const float* bnd_g = (const float*)d_in[17];
    const float* bnd_b = (const float*)d_in[18];
    const float* bnd_m = (const float*)d_in[19];
    const float* bnd_v = (const float*)d_in[20];
    const float* fc2_w = (const float*)d_in[21];
    const float* fc2_b = (const float*)d_in[22];
    float* out = (float*)d_out;

    zero_prep_kernel<<<(N_NODES + 255) / 256, 256>>>(
        conv1_b, bn1_g, bn1_b, bn1_m, bn1_v,
        conv2_b, bn2_g, bn2_b, bn2_m, bn2_v,
        fc1_b,   bnd_g, bnd_b, bnd_m, bnd_v);

    count_kernel<<<(N_EDGES / 4 + 255) / 256, 256>>>(ei);
    scanA_kernel<<<NBLK, 256>>>();          // dis + chunk sums
    scanB_kernel<<<1, 128>>>();
    scanC_kernel<<<NBLK, 256>>>();
    fill_kernel<<<(N_EDGES / 4 + 255) / 256, 256>>>(ei);

    // xs = x * dis[row]  (wide grid)
    scale_x_kernel<<<(N_NODES * (IN_CH / 4) + 255) / 256, 256>>>(x);
    // a = dis[n] * sum xs[src]
    agg64_kernel<<<(N_NODES * 32 + 255) / 256, 256>>>();
    // h2 = relu(bn1(a@W1 + cb1)) @ W2 * dis[row]   (fused encoder)
    enc_gemm_kernel<<<(N_NODES + ERPB - 1) / ERPB, 256>>>(conv1_w, conv2_w);
    // z = relu(bn2(dis[n] * sum h2[src] + cb2))
    agg32_kernel<<<(N_NODES * 32 + 255) / 256, 256>>>();
    // x_hat = relu(bnd(z@fc1 + b3)) @ fc2 + b4  -> d_out   (fused decoder)
    dec_gemm_kernel<<<(N_NODES + DRPB - 1) / DRPB, 256>>>(fc1_w, fc2_w, fc2_b, out);
    // z_graph -> d_out[6.4M:]
    pool_kernel<<<N_GRAPHS, 256>>>(batch, out + (size_t)N_NODES * IN_CH);
}

// round 17
// speedup vs baseline: 1.0549x; 1.0092x over previous
#include <cuda_runtime.h>
#include <cstdint>

// ---------------- problem constants ----------------
constexpr int N_NODES  = 100000;
constexpr int N_EDGES  = 3200000;
constexpr int N_GRAPHS = 64;
constexpr int IN_CH  = 64;
constexpr int HID_CH = 128;
constexpr int LAT    = 32;
constexpr float EPS  = 1e-5f;
constexpr int SCAN_CHUNK = 1024;
constexpr int NBLK = (N_NODES + SCAN_CHUNK - 1) / SCAN_CHUNK;   // 98

// ---------------- scratch (device globals) ----------------
__device__ __align__(16) int   g_count[N_NODES];
__device__ __align__(16) int   g_rowptr[N_NODES + 1];
__device__ __align__(16) int   g_cur[N_NODES];
__device__ __align__(16) int   g_src[N_EDGES];
__device__ __align__(16) int   g_bsum[NBLK];
__device__ __align__(16) int   g_boff[NBLK];
__device__ __align__(16) float g_dis[N_NODES];
__device__ __align__(16) float g_a  [(size_t)N_NODES * IN_CH];   // agg(x*dis)
__device__ __align__(16) float g_xs [(size_t)N_NODES * IN_CH];   // x * dis[row]
__device__ __align__(16) float g_h2 [(size_t)N_NODES * LAT];     // enc out (pre-agg)
__device__ __align__(16) float g_z  [(size_t)N_NODES * LAT];     // z_nodes
__device__ __align__(16) float g_s1[HID_CH];
__device__ __align__(16) float g_t1[HID_CH];
__device__ __align__(16) float g_s2[LAT];
__device__ __align__(16) float g_t2[LAT];
__device__ __align__(16) float g_sd[HID_CH];
__device__ __align__(16) float g_td[HID_CH];

// ---------------- zero counters + BN prep (fused) ----------------
__global__ void zero_prep_kernel(
    const float* __restrict__ conv1_b,
    const float* __restrict__ bn1_g, const float* __restrict__ bn1_b,
    const float* __restrict__ bn1_m, const float* __restrict__ bn1_v,
    const float* __restrict__ conv2_b,
    const float* __restrict__ bn2_g, const float* __restrict__ bn2_b,
    const float* __restrict__ bn2_m, const float* __restrict__ bn2_v,
    const float* __restrict__ fc1_b,
    const float* __restrict__ bnd_g, const float* __restrict__ bnd_b,
    const float* __restrict__ bnd_m, const float* __restrict__ bnd_v)
{
    int i = blockIdx.x * blockDim.x + threadIdx.x;
    if (i < N_NODES) g_count[i] = 0;
    if (blockIdx.x == 0) {
        int c = threadIdx.x;
        if (c < HID_CH) {
            float s = bn1_g[c] * rsqrtf(bn1_v[c] + EPS);
            g_s1[c] = s;
            g_t1[c] = (conv1_b[c] - bn1_m[c]) * s + bn1_b[c];
            float sd = bnd_g[c] * rsqrtf(bnd_v[c] + EPS);
            g_sd[c] = sd;
            g_td[c] = (fc1_b[c] - bnd_m[c]) * sd + bnd_b[c];
        }
        if (c < LAT) {
            float s = bn2_g[c] * rsqrtf(bn2_v[c] + EPS);
            g_s2[c] = s;
            g_t2[c] = (conv2_b[c] - bn2_m[c]) * s + bn2_b[c];
        }
    }
}

// ---------------- CSR build (edge_index is INT32; vectorized int4) ------------
__global__ void count_kernel(const int* __restrict__ ei) {
    int e4 = blockIdx.x * blockDim.x + threadIdx.x;
    if (e4 >= N_EDGES / 4) return;
    int4 c = ((const int4*)(ei + N_EDGES))[e4];
    atomicAdd(&g_count[c.x], 1);
    atomicAdd(&g_count[c.y], 1);
    atomicAdd(&g_count[c.z], 1);
    atomicAdd(&g_count[c.w], 1);
}

// per-chunk sums + dis
__global__ void scanA_kernel() {
    __shared__ int sh[256];
    int t = threadIdx.x;
    int base = blockIdx.x * SCAN_CHUNK + t * 4;
    int s = 0;
    #pragma unroll
    for (int k = 0; k < 4; k++) {
        int i = base + k;
        if (i < N_NODES) {
            int d = g_count[i];
            s += d;
            g_dis[i] = d > 0 ? rsqrtf((float)d) : 0.0f;
        }
    }
    sh[t] = s; __syncthreads();
    for (int d = 128; d > 0; d >>= 1) {
        if (t < d) sh[t] += sh[t + d];
        __syncthreads();
    }
    if (t == 0) g_bsum[blockIdx.x] = sh[0];
}

// parallel scan of the 98 chunk sums
__global__ void scanB_kernel() {
    __shared__ int sh[128];
    int t = threadIdx.x;
    int v = (t < NBLK) ? g_bsum[t] : 0;
    sh[t] = v; __syncthreads();
    for (int d = 1; d < 128; d <<= 1) {
        int tmp = (t >= d) ? sh[t - d] : 0;
        __syncthreads();
        sh[t] += tmp;
        __syncthreads();
    }
    if (t < NBLK) g_boff[t] = sh[t] - v;           // exclusive
    if (t == NBLK - 1) g_rowptr[N_NODES] = sh[t];
}

__global__ void scanC_kernel() {
    __shared__ int sh[256];
    int t = threadIdx.x;
    int base = blockIdx.x * SCAN_CHUNK + t * 4;
    int v[4]; int s = 0;
    #pragma unroll
    for (int k = 0; k < 4; k++) {
        int i = base + k;
        v[k] = (i < N_NODES) ? g_count[i] : 0;
        s += v[k];
    }
    sh[t] = s; __syncthreads();
    for (int d = 1; d < 256; d <<= 1) {
        int tmp = (t >= d) ? sh[t - d] : 0;
        __syncthreads();
        sh[t] += tmp;
        __syncthreads();
    }
    int off = g_boff[blockIdx.x] + sh[t] - s;   // exclusive
    #pragma unroll
    for (int k = 0; k < 4; k++) {
        int i = base + k;
        if (i < N_NODES) { g_rowptr[i] = off; g_cur[i] = off; off += v[k]; }
    }
}

__global__ void fill_kernel(const int* __restrict__ ei) {
    int e4 = blockIdx.x * blockDim.x + threadIdx.x;
    if (e4 >= N_EDGES / 4) return;
    int4 r = ((const int4*)ei)[e4];
    int4 c = ((const int4*)(ei + N_EDGES))[e4];
    g_src[atomicAdd(&g_cur[c.x], 1)] = r.x;
    g_src[atomicAdd(&g_cur[c.y], 1)] = r.y;
    g_src[atomicAdd(&g_cur[c.z], 1)] = r.z;
    g_src[atomicAdd(&g_cur[c.w], 1)] = r.w;
}

// ---------------- xs = x * dis[row]  (standalone, wide grid) ------------------
__global__ void scale_x_kernel(const float* __restrict__ x) {
    int i = blockIdx.x * 256 + threadIdx.x;                // float4 index
    if (i >= N_NODES * (IN_CH / 4)) return;
    int row = i >> 4;
    float d = g_dis[row];
    float4 v = ((const float4*)x)[i];
    v.x *= d; v.y *= d; v.z *= d; v.w *= d;
    ((float4*)g_xs)[i] = v;
}

// ---------------- agg64: a[n] = dis[n] * sum xs[src]  (warp/node) -------------
// R11 loop structure (no prefetch — measured regression); dual accumulators
// to halve the FADD dependency chain.
__global__ void agg64_kernel() {
    int w = (blockIdx.x * blockDim.x + threadIdx.x) >> 5;
    if (w >= N_NODES) return;
    int lane = threadIdx.x & 31;
    int beg = g_rowptr[w], end = g_rowptr[w + 1];
    float2 acc0 = make_float2(0.f, 0.f);
    float2 acc1 = make_float2(0.f, 0.f);
    int i = beg;
    for (; i + 32 <= end; i += 32) {
        int myr = g_src[i + lane];
        #pragma unroll
        for (int j = 0; j < 32; j += 2) {
            int r0 = __shfl_sync(0xffffffffu, myr, j);
            int r1 = __shfl_sync(0xffffffffu, myr, j + 1);
            float2 v0 = ((const float2*)g_xs)[r0 * (IN_CH / 2) + lane];
            float2 v1 = ((const float2*)g_xs)[r1 * (IN_CH / 2) + lane];
            acc0.x += v0.x; acc0.y += v0.y;
            acc1.x += v1.x; acc1.y += v1.y;
        }
    }
    if (i < end) {
        int cnt = end - i;
        int myr = (i + lane < end) ? g_src[i + lane] : 0;
        #pragma unroll 4
        for (int j = 0; j < cnt; j++) {
            int r = __shfl_sync(0xffffffffu, myr, j);
            float2 v = ((const float2*)g_xs)[r * (IN_CH / 2) + lane];
            acc0.x += v.x;
            acc0.y += v.y;
        }
    }
    float dc = g_dis[w];
    float2 o = make_float2((acc0.x + acc1.x) * dc, (acc0.y + acc1.y) * dc);
    ((float2*)g_a)[w * (IN_CH / 2) + lane] = o;
}

// ---------------- agg32: z[n] = relu(bn2(dis[n] * sum h2[src])) ---------------
__global__ void agg32_kernel() {
    int w = (blockIdx.x * blockDim.x + threadIdx.x) >> 5;
    if (w >= N_NODES) return;
    int lane = threadIdx.x & 31;
    int beg = g_rowptr[w], end = g_rowptr[w + 1];
    float acc0 = 0.f, acc1 = 0.f;
    int i = beg;
    for (; i + 32 <= end; i += 32) {
        int myr = g_src[i + lane];
        #pragma unroll
        for (int j = 0; j < 32; j += 2) {
            int r0 = __shfl_sync(0xffffffffu, myr, j);
            int r1 = __shfl_sync(0xffffffffu, myr, j + 1);
            acc0 += g_h2[r0 * LAT + lane];
            acc1 += g_h2[r1 * LAT + lane];
        }
    }
    if (i < end) {
        int cnt = end - i;
        int myr = (i + lane < end) ? g_src[i + lane] : 0;
        #pragma unroll 4
        for (int j = 0; j < cnt; j++) {
            int r = __shfl_sync(0xffffffffu, myr, j);
            acc0 += g_h2[r * LAT + lane];
        }
    }
    float acc = (acc0 + acc1) * g_dis[w];
    g_z[w * LAT + lane] = fmaxf(fmaf(acc, g_s2[lane], g_t2[lane]), 0.f);
}

// ---------------- fused encoder GEMM: h2 = relu(bn1(a@W1)) @ W2 * dis ---------
constexpr int ERPB = 32;
__global__ void __launch_bounds__(256) enc_gemm_kernel(const float* __restrict__ W1,
                                                       const float* __restrict__ W2)
{
    __shared__ alignas(16) float W2sh[HID_CH * LAT];     // 16 KB
    __shared__ alignas(16) float Xsh[ERPB * IN_CH];      // 8 KB
    __shared__ alignas(16) float B1sh[ERPB * 132];       // 16.5 KB (padded rows)
    const int tid = threadIdx.x;
    const int base = blockIdx.x * ERPB;

    for (int i = tid; i < HID_CH * LAT / 4; i += 256)
        ((float4*)W2sh)[i] = ((const float4*)W2)[i];
    for (int i = tid; i < ERPB * IN_CH / 4; i += 256) {
        int row = (i * 4) >> 6;
        float4 v = make_float4(0.f, 0.f, 0.f, 0.f);
        if (base + row < N_NODES) v = ((const float4*)g_a)[(size_t)base * 16 + i];
        ((float4*)Xsh)[i] = v;
    }
    __syncthreads();

    // stage 1: B1 = relu(bn1(X @ W1)); CQ=32, TM=4
    {
        int cx = tid & 31, ry = tid >> 5;
        float4 acc[4];
        #pragma unroll
        for (int m = 0; m < 4; m++) acc[m] = make_float4(0.f, 0.f, 0.f, 0.f);
        #pragma unroll 8
        for (int k = 0; k < IN_CH; k++) {
            float4 wv = ((const float4*)W1)[k * 32 + cx];     // L1-resident (32 KB)
            #pragma unroll
            for (int m = 0; m < 4; m++) {
                float xv = Xsh[(ry * 4 + m) * IN_CH + k];
                acc[m].x = fmaf(xv, wv.x, acc[m].x);
                acc[m].y = fmaf(xv, wv.y, acc[m].y);
                acc[m].z = fmaf(xv, wv.z, acc[m].z);
                acc[m].w = fmaf(xv, wv.w, acc[m].w);
            }
        }
        float4 sv = ((const float4*)g_s1)[cx];
        float4 tv = ((const float4*)g_t1)[cx];
        #pragma unroll
        for (int m = 0; m < 4; m++) {
            float4 o;
            o.x = fmaxf(fmaf(acc[m].x, sv.x, tv.x), 0.f);
            o.y = fmaxf(fmaf(acc[m].y, sv.y, tv.y), 0.f);
            o.z = fmaxf(fmaf(acc[m].z, sv.z, tv.z), 0.f);
            o.w = fmaxf(fmaf(acc[m].w, sv.w, tv.w), 0.f);
            ((float4*)(B1sh + (ry * 4 + m) * 132))[cx] = o;
        }
    }
    __syncthreads();

    // stage 2: h2 = (B1 @ W2) * dis[row]; CQ=8, TM=1
    {
        int cx = tid & 7, ry = tid >> 3;
        float4 acc = make_float4(0.f, 0.f, 0.f, 0.f);
        #pragma unroll 8
        for (int k = 0; k < HID_CH; k++) {
            float4 wv = ((const float4*)W2sh)[k * 8 + cx];
            float xv = B1sh[ry * 132 + k];
            acc.x = fmaf(xv, wv.x, acc.x);
            acc.y = fmaf(xv, wv.y, acc.y);
            acc.z = fmaf(xv, wv.z, acc.z);
            acc.w = fmaf(xv, wv.w, acc.w);
        }
        int row = base + ry;
        if (row < N_NODES) {
            float d = g_dis[row];
            acc.x *= d; acc.y *= d; acc.z *= d; acc.w *= d;
            ((float4*)g_h2)[(size_t)row * 8 + cx] = acc;
        }
    }
}

// ---------------- fused decoder GEMM: out = relu(bnd(z@W3)) @ W4 + b ----------
constexpr int DRPB = 32;
__global__ void __launch_bounds__(256) dec_gemm_kernel(const float* __restrict__ W3,
                                                       const float* __restrict__ W4,
                                                       const float* __restrict__ b4,
                                                       float* __restrict__ out)
{
    __shared__ alignas(16) float W3sh[LAT * HID_CH];     // 16 KB
    __shared__ alignas(16) float Zsh[DRPB * LAT];        // 4 KB
    __shared__ alignas(16) float Dsh[DRPB * 132];        // 16.5 KB
    const int tid = threadIdx.x;
    const int base = blockIdx.x * DRPB;

    for (int i = tid; i < LAT * HID_CH / 4; i += 256)
        ((float4*)W3sh)[i] = ((const float4*)W3)[i];
    for (int i = tid; i < DRPB * LAT / 4; i += 256) {
        int row = (i * 4) >> 5;
        float4 v = make_float4(0.f, 0.f, 0.f, 0.f);
        if (base + row < N_NODES) v = ((const float4*)g_z)[(size_t)base * 8 + i];
        ((float4*)Zsh)[i] = v;
    }
    __syncthreads();

    // stage 1: D = relu(bnd(Z @ W3)); CQ=32, TM=4
    {
        int cx = tid & 31, ry = tid >> 5;
        float4 acc[4];
        #pragma unroll
        for (int m = 0; m < 4; m++) acc[m] = make_float4(0.f, 0.f, 0.f, 0.f);
        #pragma unroll
        for (int k = 0; k < LAT; k++) {
            float4 wv = ((const float4*)W3sh)[k * 32 + cx];
            #pragma unroll
            for (int m = 0; m < 4; m++) {
                float xv = Zsh[(ry * 4 + m) * LAT + k];
                acc[m].x = fmaf(xv, wv.x, acc[m].x);
                acc[m].y = fmaf(xv, wv.y, acc[m].y);
                acc[m].z = fmaf(xv, wv.z, acc[m].z);
                acc[m].w = fmaf(xv, wv.w, acc[m].w);
            }
        }
        float4 sv = ((const float4*)g_sd)[cx];
        float4 tv = ((const float4*)g_td)[cx];
        #pragma unroll
        for (int m = 0; m < 4; m++) {
            float4 o;
            o.x = fmaxf(fmaf(acc[m].x, sv.x, tv.x), 0.f);
            o.y = fmaxf(fmaf(acc[m].y, sv.y, tv.y), 0.f);
            o.z = fmaxf(fmaf(acc[m].z, sv.z, tv.z), 0.f);
            o.w = fmaxf(fmaf(acc[m].w, sv.w, tv.w), 0.f);
            ((float4*)(Dsh + (ry * 4 + m) * 132))[cx] = o;
        }
    }
    __syncthreads();

    // stage 2: out = D @ W4 + b4; COUT=64, CQ=16, TM=2; W4 via L1 (32 KB)
    {
        int cx = tid & 15, ry = tid >> 4;
        float4 acc[2];
        acc[0] = make_float4(0.f, 0.f, 0.f, 0.f);
        acc[1] = make_float4(0.f, 0.f, 0.f, 0.f);
        #pragma unroll 8
        for (int k = 0; k < HID_CH; k++) {
            float4 wv = ((const float4*)W4)[k * 16 + cx];
            #pragma unroll
            for (int m = 0; m < 2; m++) {
                float xv = Dsh[(ry * 2 + m) * 132 + k];
                acc[m].x = fmaf(xv, wv.x, acc[m].x);
                acc[m].y = fmaf(xv, wv.y, acc[m].y);
                acc[m].z = fmaf(xv, wv.z, acc[m].z);
                acc[m].w = fmaf(xv, wv.w, acc[m].w);
            }
        }
        float4 bv = ((const float4*)b4)[cx];
        #pragma unroll
        for (int m = 0; m < 2; m++) {
            int row = base + ry * 2 + m;
            if (row < N_NODES) {
                float4 o = acc[m];
                o.x += bv.x; o.y += bv.y; o.z += bv.z; o.w += bv.w;
                ((float4*)out)[(size_t)row * 16 + cx] = o;
            }
        }
    }
}

// ---------------- graph mean pool: batch is SORTED int32 ----------------------
__global__ void pool_kernel(const int* __restrict__ batch, float* __restrict__ out) {
    int g = blockIdx.x;
    __shared__ int s_lo, s_hi;
    if (threadIdx.x == 0) {
        int a = 0, b = N_NODES;
        while (a < b) { int m = (a + b) >> 1; if (batch[m] < g) a = m + 1; else b = m; }
        s_lo = a;
        b = N_NODES;
        while (a < b) { int m = (a + b) >> 1; if (batch[m] < g + 1) a = m + 1; else b = m; }
        s_hi = a;
    }
    __syncthreads();
    int lo = s_lo, hi = s_hi;
    int lane = threadIdx.x & 31, wid = threadIdx.x >> 5;
    float acc = 0.f;
    for (int n = lo + wid; n < hi; n += 8)
        acc += g_z[(size_t)n * LAT + lane];
    __shared__ float sh[8][LAT];
    sh[wid][lane] = acc;
    __syncthreads();
    if (wid == 0) {
        float s = 0.f;
        #pragma unroll
        for (int k = 0; k < 8; k++) s += sh[k][lane];
        float cnt = (float)(hi - lo);
        out[g * LAT + lane] = s / fmaxf(cnt, 1.0f);
    }
}

// ---------------- launch: kernel launches ONLY ----------------
extern "C" void kernel_launch(void* const* d_in, const int* in_sizes, int n_in,
                              void* d_out, int out_size)
{
    const float* x     = (const float*)d_in[0];
    const int*   ei    = (const int*)d_in[1];      // int32
    const int*   batch = (const int*)d_in[2];      // int32
    const float* conv1_w = (const float*)d_in[3];
    const float* conv1_b = (const float*)d_in[4];
    const float* conv2_w = (const float*)d_in[5];
    const float* conv2_b = (const float*)d_in[6];
    const float* bn1_g = (const float*)d_in[7];
    const float* bn1_b = (const float*)d_in[8];
    const float* bn1_m = (const float*)d_in[9];
    const float* bn1_v = (const float*)d_in[10];
    const float* bn2_g = (const float*)d_in[11];
    const float* bn2_b = (const float*)d_in[12];
    const float* bn2_m = (const float*)d_in[13];
    const float* bn2_v = (const float*)d_in[14];
    const float* fc1_w = (const float*)d_in[15];
    const float* fc1_b = (const float*)d_in[16];
    const float* bnd_g = (const float*)d_in[17];
    const float* bnd_b = (const float*)d_in[18];
    const float* bnd_m = (const float*)d_in[19];
    const float* bnd_v = (const float*)d_in[20];
    const float* fc2_w = (const float*)d_in[21];
    const float* fc2_b = (const float*)d_in[22];
    float* out = (float*)d_out;

    zero_prep_kernel<<<(N_NODES + 255) / 256, 256>>>(
        conv1_b, bn1_g, bn1_b, bn1_m, bn1_v,
        conv2_b, bn2_g, bn2_b, bn2_m, bn2_v,
        fc1_b,   bnd_g, bnd_b, bnd_m, bnd_v);

    count_kernel<<<(N_EDGES / 4 + 255) / 256, 256>>>(ei);
    scanA_kernel<<<NBLK, 256>>>();          // dis + chunk sums
    scanB_kernel<<<1, 128>>>();
    scanC_kernel<<<NBLK, 256>>>();
    fill_kernel<<<(N_EDGES / 4 + 255) / 256, 256>>>(ei);

    // xs = x * dis[row]  (wide grid)
    scale_x_kernel<<<(N_NODES * (IN_CH / 4) + 255) / 256, 256>>>(x);
    // a = dis[n] * sum xs[src]
    agg64_kernel<<<(N_NODES * 32 + 255) / 256, 256>>>();
    // h2 = relu(bn1(a@W1 + cb1)) @ W2 * dis[row]   (fused encoder)
    enc_gemm_kernel<<<(N_NODES + ERPB - 1) / ERPB, 256>>>(conv1_w, conv2_w);
    // z = relu(bn2(dis[n] * sum h2[src] + cb2))
    agg32_kernel<<<(N_NODES * 32 + 255) / 256, 256>>>();
    // x_hat = relu(bnd(z@fc1 + b3)) @ fc2 + b4  -> d_out   (fused decoder)
    dec_gemm_kernel<<<(N_NODES + DRPB - 1) / DRPB, 256>>>(fc1_w, fc2_w, fc2_b, out);
    // z_graph -> d_out[6.4M:]
    pool_kernel<<<N_GRAPHS, 256>>>(batch, out + (size_t)N_NODES * IN_CH);
}